// round 1
// baseline (speedup 1.0000x reference)
#include <cuda_runtime.h>
#include <cuda_bf16.h>
#include <cstdint>

// MaddnessConv2d:
//   x:            (16, 64, 56, 56) f32
//   split_idxs:   (16, 4) i32   -- index within 36-dim subvector
//   split_vals:   (16, 4, 8) f32
//   lookup_tables:(16, 16, 64) f32
//   bias:         (64,) f32
//   out:          (16, 64, 56, 56) f32
//
// Key algorithmic observation: the unfold is unnecessary. Each codebook cb
// reads exactly 4 scalars of the patch: feature f = cb*36 + split_idxs[cb][t],
// which maps to (ch, ki, kj) = (f/9, (f%9)/3, f%3) of the 3x3 window
// (channel-major ordering, pad=1, stride=1). Thresholds depend on the running
// enc, the *value indices* do not. So per output pixel: 64 gathered loads,
// 16 4-level comparisons, then out[ch] = sum_cb LUT[cb][enc_cb][ch] + bias.

#define NCB   16
#define KENC  16
#define HW    3136          // 56*56
#define WID   56
#define NPIX  50176         // 16*56*56
#define TPB   128
#define NBLK  392           // 392*128 == 50176 exactly

// dynamic smem layout (16B aligned pieces):
//   float4 s_lut[16*16*16]       65536 B  (XOR-swizzled: slot j^e)
//   float  s_bias[64]              256 B
//   float  s_sval[16*4*8]         2048 B
//   int    s_off[64]               256 B
//   int    s_dy[64]                256 B
//   int    s_dx[64]                256 B
#define SMEM_BYTES (65536 + 256 + 2048 + 256 + 256 + 256)

__global__ __launch_bounds__(TPB) void maddness_conv2d_kernel(
    const float* __restrict__ x,
    const int*   __restrict__ split_idxs,
    const float* __restrict__ split_vals,
    const float* __restrict__ lut,
    const float* __restrict__ bias,
    float*       __restrict__ out)
{
    extern __shared__ char smem_raw[];
    float4* s_lut  = (float4*)smem_raw;
    float*  s_bias = (float*)(smem_raw + 65536);
    float*  s_sval = (float*)(smem_raw + 65536 + 256);
    int*    s_off  = (int*)  (smem_raw + 65536 + 256 + 2048);
    int*    s_dy   = (int*)  (smem_raw + 65536 + 256 + 2048 + 256);
    int*    s_dx   = (int*)  (smem_raw + 65536 + 256 + 2048 + 512);

    const int tid = threadIdx.x;

    // --- cooperative smem fill ---
    // LUT: logical float4 index i = (cb*16 + e)*16 + j  ->  physical slot (i & ~15) + (j ^ e)
    const float4* lut4 = (const float4*)lut;
    #pragma unroll
    for (int i = tid; i < NCB * KENC * 16; i += TPB) {
        int j = i & 15;
        int e = (i >> 4) & 15;
        s_lut[(i & ~15) | (j ^ e)] = lut4[i];
    }
    if (tid < 64) {
        int cb = tid >> 2;                     // tid = cb*4 + t
        int si = split_idxs[tid];
        int f  = cb * 36 + si;
        int ch = f / 9;
        int r  = f - ch * 9;
        int dy = r / 3 - 1;
        int dx = r - (r / 3) * 3 - 1;
        s_off[tid] = ch * HW + dy * WID + dx;
        s_dy[tid]  = dy;
        s_dx[tid]  = dx;
        s_bias[tid] = bias[tid];
    }
    #pragma unroll
    for (int i = tid; i < NCB * 32; i += TPB) s_sval[i] = split_vals[i];
    __syncthreads();

    // --- per-pixel work ---
    const int p   = blockIdx.x * TPB + tid;    // grid sized exactly: p < NPIX always
    const int b   = p / HW;
    const int rem = p - b * HW;
    const int y   = rem / WID;
    const int xw  = rem - y * WID;
    const float* xb = x + (size_t)b * 64 * HW + rem;

    float4 acc[16];
    const float4* bias4 = (const float4*)s_bias;
    #pragma unroll
    for (int j = 0; j < 16; j++) acc[j] = bias4[j];

    #pragma unroll
    for (int cb = 0; cb < NCB; cb++) {
        int e = 0;
        #pragma unroll
        for (int t = 0; t < 4; t++) {
            const int idx = cb * 4 + t;
            const int dy = s_dy[idx];
            const int dx = s_dx[idx];
            float v = 0.0f;
            if ((unsigned)(y + dy) < 56u && (unsigned)(xw + dx) < 56u)
                v = __ldg(xb + s_off[idx]);
            const float thr = s_sval[cb * 32 + t * 8 + e];
            e = 2 * e + (v >= thr ? 1 : 0);
        }
        const float4* row = s_lut + (cb * 16 + e) * 16;
        #pragma unroll
        for (int j = 0; j < 16; j++) {
            float4 v = row[j ^ e];
            acc[j].x += v.x;
            acc[j].y += v.y;
            acc[j].z += v.z;
            acc[j].w += v.w;
        }
    }

    // --- write: out[b][ch][y][x]; warp lanes are consecutive pixels -> coalesced per ch ---
    float* ob = out + (size_t)b * 64 * HW + rem;
    #pragma unroll
    for (int j = 0; j < 16; j++) {
        ob[(4 * j + 0) * HW] = acc[j].x;
        ob[(4 * j + 1) * HW] = acc[j].y;
        ob[(4 * j + 2) * HW] = acc[j].z;
        ob[(4 * j + 3) * HW] = acc[j].w;
    }
}

extern "C" void kernel_launch(void* const* d_in, const int* in_sizes, int n_in,
                              void* d_out, int out_size)
{
    const float* x    = (const float*)d_in[0];
    const int*   sidx = (const int*)  d_in[1];
    const float* sval = (const float*)d_in[2];
    const float* lut  = (const float*)d_in[3];
    const float* bias = (const float*)d_in[4];
    float* out = (float*)d_out;

    // >48KB dynamic smem needs the attribute; immediate host-side call,
    // not a stream op, safe under graph capture. Idempotent.
    cudaFuncSetAttribute(maddness_conv2d_kernel,
                         cudaFuncAttributeMaxDynamicSharedMemorySize,
                         SMEM_BYTES);

    maddness_conv2d_kernel<<<NBLK, TPB, SMEM_BYTES>>>(x, sidx, sval, lut, bias, out);
}